// round 14
// baseline (speedup 1.0000x reference)
#include <cuda_runtime.h>
#include <cuda_fp16.h>
#include <cstdint>
#include <cstddef>

// ---------------------------------------------------------------------------
// Problem dims
// ---------------------------------------------------------------------------
#define B_DIM   128
#define L_DIM   512
#define IN_DIM  512
#define MEM     1024
#define NOUT    2048
#define M_DIM   (B_DIM * L_DIM)      // 65536

#define NCHUNK  16                   // 8 chunks c1-phase + 8 chunks io-phase

// ---------------------------------------------------------------------------
// Device scratch (static allocation — no runtime alloc)
// g_embh2: [M][1024] __half2 — .x = sb = 5*tanh((c1+b)/5), .y = io + b_io
// g_A2   : [mt(512)][chunk(8)][128 rows][64 cols] fp16, SW128-swizzled 16KB blocks
// g_W2   : [wt(16)][chunk(8)][128 rows][64 cols] fp16 (wt 0-7 = c1 cols, 8-15 = io)
// ---------------------------------------------------------------------------
__device__ __half2 g_embh2[(size_t)M_DIM * MEM];    // 256 MB
__device__ __half  g_A2[(size_t)M_DIM * 512];       // 64 MB
__device__ __half  g_W2[(size_t)NOUT * 512];        // 2 MB

// ---------------------------------------------------------------------------
// Helpers
// ---------------------------------------------------------------------------
__device__ __forceinline__ uint32_t smem_u32(const void* p) {
    uint32_t a;
    asm("{ .reg .u64 t; cvta.to.shared.u64 t, %1; cvt.u32.u64 %0, t; }" : "=r"(a) : "l"(p));
    return a;
}
__device__ __forceinline__ uint32_t swz(uint32_t b) { return b ^ ((b >> 3) & 0x70); }

__device__ __forceinline__ void cp_async16(uint32_t dst, const void* src) {
    asm volatile("cp.async.cg.shared.global [%0], [%1], 16;" :: "r"(dst), "l"(src) : "memory");
}
__device__ __forceinline__ void cp_commit() {
    asm volatile("cp.async.commit_group;" ::: "memory");
}
template <int N>
__device__ __forceinline__ void cp_wait() {
    asm volatile("cp.async.wait_group %0;" :: "n"(N) : "memory");
}

#define LDSM4(r0, r1, r2, r3, a) \
    asm volatile("ldmatrix.sync.aligned.m8n8.x4.shared.b16 {%0,%1,%2,%3}, [%4];" \
                 : "=r"(r0), "=r"(r1), "=r"(r2), "=r"(r3) : "r"(a))

#define MMA16816(c0, c1, c2, c3, a0, a1, a2, a3, b0, b1) \
    asm volatile("mma.sync.aligned.m16n8k16.row.col.f32.f16.f16.f32 " \
                 "{%0,%1,%2,%3}, {%4,%5,%6,%7}, {%8,%9}, {%0,%1,%2,%3};" \
                 : "+f"(c0), "+f"(c1), "+f"(c2), "+f"(c3) \
                 : "r"(a0), "r"(a1), "r"(a2), "r"(a3), "r"(b0), "r"(b1))

// Accurate fast tanh (epilogue only; error ~1e-6)
__device__ __forceinline__ float tanh_fast(float x) {
    float a = fabsf(x);
    float e = __expf(-2.0f * a);
    float r = __fdividef(1.0f - e, 1.0f + e);
    return copysignf(r, x);
}

// HW tanh (MUFU.TANH, sm_75+): single instruction
__device__ __forceinline__ float tanh_hw(float x) {
    float r;
    asm("tanh.approx.f32 %0, %1;" : "=f"(r) : "f"(x));
    return r;
}

// ---------------------------------------------------------------------------
// Conversion kernels: fp32 -> fp16 single-rounded, tiled + SW128 pre-swizzled
// ---------------------------------------------------------------------------
__global__ __launch_bounds__(256) void conv_a_kernel(const float* __restrict__ u) {
    int idx = blockIdx.x * 256 + threadIdx.x;      // 8,388,608 threads
    int m = idx >> 8;
    int k = (idx & 255) * 2;
    float2 v = *(const float2*)(u + (size_t)m * IN_DIM + k);
    __half h0 = __float2half_rn(v.x);
    __half h1 = __float2half_rn(v.y);
    uint32_t hp = (uint32_t)*(unsigned short*)&h0 | ((uint32_t)*(unsigned short*)&h1 << 16);
    int mt = m >> 7, r = m & 127;
    int ch = k >> 6, c = k & 63;
    uint32_t off = swz((uint32_t)(r * 128 + c * 2));
    char* base = (char*)g_A2;
    *(uint32_t*)(base + (((size_t)(mt * 8 + ch)) << 14) + off) = hp;
}

__global__ __launch_bounds__(256) void conv_w_kernel(const float* __restrict__ W) {
    int idx = blockIdx.x * 256 + threadIdx.x;      // 524,288 threads
    int n = idx >> 8;
    int k = (idx & 255) * 2;
    float2 v = *(const float2*)(W + (size_t)n * IN_DIM + k);
    __half h0 = __float2half_rn(v.x);
    __half h1 = __float2half_rn(v.y);
    uint32_t hp = (uint32_t)*(unsigned short*)&h0 | ((uint32_t)*(unsigned short*)&h1 << 16);
    int nt = n >> 7, r = n & 127;
    int ch = k >> 6, c = k & 63;
    uint32_t off = swz((uint32_t)(r * 128 + c * 2));
    char* base = (char*)g_W2;
    *(uint32_t*)(base + (((size_t)(nt * 8 + ch)) << 14) + off) = hp;
}

// ---------------------------------------------------------------------------
// fp16 warp-MMA GEMM, two-phase, in-register sb.
// CTA tile 128x128, BK=64, 128 threads (4 warps, 2x2, warp tile 64x64).
// Phase A (chunks 0-7):  acc = A * W_c1 -> sb = 5*tanh((acc+b)/5) packed to regs
// Phase B (chunks 8-15): acc = A * W_io -> store uint2{(sb0,io0),(sb1,io1)}
// 3-stage cp.async pipeline, 96 KB smem, 2 CTAs/SM. Grid (8, 512).
// ---------------------------------------------------------------------------
#define NST 3
#define STAGE_BYTES 32768                     // A 16KB + B 16KB
#define SMEM_TOTAL (NST * STAGE_BYTES)        // 96 KB

__global__ __launch_bounds__(128, 2) void gemm_mma_kernel(const float* __restrict__ bias) {
    extern __shared__ __align__(1024) char smem[];
    const uint32_t sm   = smem_u32(smem);
    const int tid  = threadIdx.x;
    const int wid  = tid >> 5;
    const int lane = tid & 31;
    const int nt   = blockIdx.x;     // 0..7  (mem cols nt*128..nt*128+127)
    const int mt   = blockIdx.y;     // 0..511
    const int wm   = wid >> 1;       // 0..1
    const int wn   = wid & 1;        // 0..1

    const char* Ab    = (const char*)g_A2 + ((size_t)mt << 17);        // mt * 8 * 16KB
    const char* Bb_c1 = (const char*)g_W2 + ((size_t)nt << 17);        // wt = nt
    const char* Bb_io = (const char*)g_W2 + ((size_t)(nt + 8) << 17);  // wt = nt + 8

    float acc[4][8][4];
#pragma unroll
    for (int i = 0; i < 4; i++)
#pragma unroll
        for (int j = 0; j < 8; j++)
#pragma unroll
            for (int e = 0; e < 4; e++) acc[i][j][e] = 0.0f;

    uint32_t sbs[4][8][2];           // packed half2 sb, filled at end of phase A

    // ldmatrix per-lane addressing (SW128): phys = row*128 + ((c16 ^ (row&7))*16)
    const int jj = lane >> 3;        // matrix index 0..3
    const int rl = lane & 7;
    uint32_t arow[4], brow[4];
#pragma unroll
    for (int mi = 0; mi < 4; mi++)
        arow[mi] = (uint32_t)((wm * 64 + mi * 16 + (jj & 1) * 8 + rl) * 128);
#pragma unroll
    for (int p = 0; p < 4; p++)
        brow[p] = (uint32_t)((wn * 64 + p * 16 + (jj & 1) * 8 + rl) * 128);

    auto load_stage = [&](int c, int s) {
        const char* As = Ab + ((size_t)(c & 7) << 14);
        const char* Bs = (c < 8) ? (Bb_c1 + ((size_t)c << 14))
                                 : (Bb_io + ((size_t)(c - 8) << 14));
        uint32_t dst = sm + (uint32_t)s * STAGE_BYTES;
#pragma unroll
        for (int i = 0; i < 8; i++) {
            uint32_t off = (uint32_t)(tid + i * 128) * 16;
            cp_async16(dst + off, As + off);
        }
#pragma unroll
        for (int i = 0; i < 8; i++) {
            uint32_t off = (uint32_t)(tid + i * 128) * 16;
            cp_async16(dst + 16384 + off, Bs + off);
        }
        cp_commit();
    };

    load_stage(0, 0);
    load_stage(1, 1);

    for (int ck = 0; ck < NCHUNK; ck++) {
        const int s = ck % NST;
        cp_wait<1>();
        __syncthreads();
        if (ck + 2 < NCHUNK) load_stage(ck + 2, (ck + 2) % NST);

        const uint32_t sA = sm + (uint32_t)s * STAGE_BYTES;
        const uint32_t sB = sA + 16384;

#pragma unroll
        for (int ks = 0; ks < 4; ks++) {
            const uint32_t cb = (uint32_t)(((2 * ks + (jj >> 1)) ^ rl) * 16);
            uint32_t a[4][4], br[4][4];
#pragma unroll
            for (int mi = 0; mi < 4; mi++)
                LDSM4(a[mi][0], a[mi][1], a[mi][2], a[mi][3], sA + arow[mi] + cb);
#pragma unroll
            for (int p = 0; p < 4; p++)
                LDSM4(br[p][0], br[p][1], br[p][2], br[p][3], sB + brow[p] + cb);
#pragma unroll
            for (int mi = 0; mi < 4; mi++) {
#pragma unroll
                for (int ni = 0; ni < 8; ni++) {
                    const int p = ni >> 1, sub = ni & 1;
                    MMA16816(acc[mi][ni][0], acc[mi][ni][1], acc[mi][ni][2], acc[mi][ni][3],
                             a[mi][0], a[mi][1], a[mi][2], a[mi][3],
                             br[p][sub], br[p][sub + 2]);
                }
            }
        }

        // Phase-A epilogue: sb -> packed half2 registers, reset acc for phase B.
        if (ck == 7) {
            const int n0 = nt * 128;
#pragma unroll
            for (int mi = 0; mi < 4; mi++) {
#pragma unroll
                for (int ni = 0; ni < 8; ni++) {
                    const int col = n0 + wn * 64 + ni * 8 + (lane & 3) * 2;
                    const float2 b2 = *(const float2*)(bias + col);
                    float s0 = 5.0f * tanh_fast((acc[mi][ni][0] + b2.x) * 0.2f);
                    float s1 = 5.0f * tanh_fast((acc[mi][ni][1] + b2.y) * 0.2f);
                    float s2 = 5.0f * tanh_fast((acc[mi][ni][2] + b2.x) * 0.2f);
                    float s3 = 5.0f * tanh_fast((acc[mi][ni][3] + b2.y) * 0.2f);
                    __half2 p01 = __floats2half2_rn(s0, s1);
                    __half2 p23 = __floats2half2_rn(s2, s3);
                    sbs[mi][ni][0] = *(uint32_t*)&p01;
                    sbs[mi][ni][1] = *(uint32_t*)&p23;
                    acc[mi][ni][0] = 0.0f; acc[mi][ni][1] = 0.0f;
                    acc[mi][ni][2] = 0.0f; acc[mi][ni][3] = 0.0f;
                }
            }
        }
    }

    // Final epilogue: io = acc + bias_io; store uint2 pairs (sb,io)(sb,io).
    const int n0 = nt * 128;
#pragma unroll
    for (int mi = 0; mi < 4; mi++) {
        const int row0 = mt * 128 + wm * 64 + mi * 16 + (lane >> 2);
#pragma unroll
        for (int ni = 0; ni < 8; ni++) {
            const int memc = n0 + wn * 64 + ni * 8 + (lane & 3) * 2;
            const float2 b2 = *(const float2*)(bias + MEM + memc);
            uint32_t io0 = (uint32_t)__half_as_ushort(__float2half_rn(acc[mi][ni][0] + b2.x));
            uint32_t io1 = (uint32_t)__half_as_ushort(__float2half_rn(acc[mi][ni][1] + b2.y));
            uint32_t io2 = (uint32_t)__half_as_ushort(__float2half_rn(acc[mi][ni][2] + b2.x));
            uint32_t io3 = (uint32_t)__half_as_ushort(__float2half_rn(acc[mi][ni][3] + b2.y));
            uint32_t s01 = sbs[mi][ni][0];
            uint32_t s23 = sbs[mi][ni][1];
            uint2 w0, w1;
            w0.x = (s01 & 0xFFFFu) | (io0 << 16);   // (sb0, io0)
            w0.y = (s01 >> 16)     | (io1 << 16);   // (sb1, io1)
            w1.x = (s23 & 0xFFFFu) | (io2 << 16);   // (sb2, io2)
            w1.y = (s23 >> 16)     | (io3 << 16);   // (sb3, io3)
            __stcs((uint2*)&g_embh2[(size_t)row0 * MEM + memc],       w0);
            __stcs((uint2*)&g_embh2[(size_t)(row0 + 8) * MEM + memc], w1);
        }
    }
}

// ---------------------------------------------------------------------------
// Phase 2: sequential scan over L. TWO mem lanes per thread — one LDG.64 +
// one STG.64 per iteration (halves LSU instruction count vs 1 lane/thread).
//   hfn = tanh(x),  eps = 1.35 + 0.45*tanh(5(hf-0.5)),  hsn = hs + eps*(hf-hs)
// out layout: h_t [B][L][MEM] ++ hf_last [B][MEM]
// ---------------------------------------------------------------------------
__global__ __launch_bounds__(128) void scan_kernel(const float* __restrict__ h0,
                                                   float* __restrict__ out)
{
    const int idx  = blockIdx.x * 128 + threadIdx.x;   // 0 .. 65535
    const int b    = idx >> 9;
    const int mem0 = (idx & 511) * 2;

    const float2 hf2 = *(const float2*)(h0 + (size_t)b * MEM + mem0);
    const float2 hs2 = *(const float2*)(h0 + (size_t)(B_DIM + b) * MEM + mem0);
    float hf0 = hf2.x, hf1 = hf2.y;
    float hs0 = hs2.x, hs1 = hs2.y;

    const uint2* e = (const uint2*)(g_embh2 + (size_t)b * L_DIM * MEM + mem0);
    float2*      o = (float2*)(out + (size_t)b * L_DIM * MEM + mem0);

#pragma unroll 8
    for (int l = 0; l < L_DIM; l++) {
        const uint2 w = e[(size_t)l * (MEM / 2)];
        const float2 v0 = __half22float2(*(const __half2*)&w.x);   // (sb0, io0)
        const float2 v1 = __half22float2(*(const __half2*)&w.y);   // (sb1, io1)

        const float hsb0 = hs0 + 0.4f;
        const float hsb1 = hs1 + 0.4f;
        const float x0   = v0.x + v0.y + 4.0f * hf0 - 7.0f * hsb0 * hsb0;
        const float x1   = v1.x + v1.y + 4.0f * hf1 - 7.0f * hsb1 * hsb1;
        const float hfn0 = tanh_hw(x0);
        const float hfn1 = tanh_hw(x1);
        const float eps0 = fmaf(0.45f, tanh_hw((hf0 - 0.5f) * 5.0f), 1.35f);
        const float eps1 = fmaf(0.45f, tanh_hw((hf1 - 0.5f) * 5.0f), 1.35f);
        hs0 = fmaf(eps0, hf0 - hs0, hs0);
        hs1 = fmaf(eps1, hf1 - hs1, hs1);

        o[(size_t)l * (MEM / 2)] = make_float2(hfn0, hfn1);
        hf0 = hfn0;
        hf1 = hfn1;
    }
    *(float2*)(out + (size_t)M_DIM * MEM + (size_t)b * MEM + mem0) = make_float2(hf0, hf1);
}

// ---------------------------------------------------------------------------
// Launch
// ---------------------------------------------------------------------------
extern "C" void kernel_launch(void* const* d_in, const int* in_sizes, int n_in,
                              void* d_out, int out_size)
{
    const float* u    = (const float*)d_in[0];   // (128, 512, 512)
    const float* h0   = (const float*)d_in[1];   // (2, 128, 1024)
    const float* W    = (const float*)d_in[2];   // (2048, 512)
    const float* bias = (const float*)d_in[3];   // (2048,)
    float* out = (float*)d_out;

    cudaFuncSetAttribute(gemm_mma_kernel, cudaFuncAttributeMaxDynamicSharedMemorySize, SMEM_TOTAL);

    conv_a_kernel<<<(M_DIM * IN_DIM / 2) / 256, 256>>>(u);   // 32768 blocks
    conv_w_kernel<<<(NOUT * IN_DIM / 2) / 256, 256>>>(W);    // 2048 blocks

    dim3 grid(8, 512);
    gemm_mma_kernel<<<grid, 128, SMEM_TOTAL>>>(bias);

    scan_kernel<<<(B_DIM * MEM / 2) / 128, 128>>>(h0, out);
}

// round 15
// speedup vs baseline: 1.0214x; 1.0214x over previous
#include <cuda_runtime.h>
#include <cuda_fp16.h>
#include <cstdint>
#include <cstddef>

// ---------------------------------------------------------------------------
// Problem dims
// ---------------------------------------------------------------------------
#define B_DIM   128
#define L_DIM   512
#define IN_DIM  512
#define MEM     1024
#define NOUT    2048
#define M_DIM   (B_DIM * L_DIM)      // 65536

#define NCHUNK  16                   // 8 chunks c1-phase + 8 chunks io-phase

// ---------------------------------------------------------------------------
// Device scratch (static allocation — no runtime alloc)
// g_embh2: [M][1024] __half2 — .x = sb = 5*tanh((c1+b)/5), .y = io + b_io
// g_A2   : [mt(512)][chunk(8)][128 rows][64 cols] fp16, SW128-swizzled 16KB blocks
// g_W2   : [wt(16)][chunk(8)][128 rows][64 cols] fp16 (wt 0-7 = c1 cols, 8-15 = io)
// ---------------------------------------------------------------------------
__device__ __half2 g_embh2[(size_t)M_DIM * MEM];    // 256 MB
__device__ __half  g_A2[(size_t)M_DIM * 512];       // 64 MB
__device__ __half  g_W2[(size_t)NOUT * 512];        // 2 MB

// ---------------------------------------------------------------------------
// Helpers
// ---------------------------------------------------------------------------
__device__ __forceinline__ uint32_t smem_u32(const void* p) {
    uint32_t a;
    asm("{ .reg .u64 t; cvta.to.shared.u64 t, %1; cvt.u32.u64 %0, t; }" : "=r"(a) : "l"(p));
    return a;
}
__device__ __forceinline__ uint32_t swz(uint32_t b) { return b ^ ((b >> 3) & 0x70); }

__device__ __forceinline__ void cp_async16(uint32_t dst, const void* src) {
    asm volatile("cp.async.cg.shared.global [%0], [%1], 16;" :: "r"(dst), "l"(src) : "memory");
}
__device__ __forceinline__ void cp_commit() {
    asm volatile("cp.async.commit_group;" ::: "memory");
}
template <int N>
__device__ __forceinline__ void cp_wait() {
    asm volatile("cp.async.wait_group %0;" :: "n"(N) : "memory");
}

#define LDSM4(r0, r1, r2, r3, a) \
    asm volatile("ldmatrix.sync.aligned.m8n8.x4.shared.b16 {%0,%1,%2,%3}, [%4];" \
                 : "=r"(r0), "=r"(r1), "=r"(r2), "=r"(r3) : "r"(a))

#define MMA16816(c0, c1, c2, c3, a0, a1, a2, a3, b0, b1) \
    asm volatile("mma.sync.aligned.m16n8k16.row.col.f32.f16.f16.f32 " \
                 "{%0,%1,%2,%3}, {%4,%5,%6,%7}, {%8,%9}, {%0,%1,%2,%3};" \
                 : "+f"(c0), "+f"(c1), "+f"(c2), "+f"(c3) \
                 : "r"(a0), "r"(a1), "r"(a2), "r"(a3), "r"(b0), "r"(b1))

// Accurate fast tanh (epilogue only; error ~1e-6)
__device__ __forceinline__ float tanh_fast(float x) {
    float a = fabsf(x);
    float e = __expf(-2.0f * a);
    float r = __fdividef(1.0f - e, 1.0f + e);
    return copysignf(r, x);
}

// HW tanh (MUFU.TANH, sm_75+): single instruction
__device__ __forceinline__ float tanh_hw(float x) {
    float r;
    asm("tanh.approx.f32 %0, %1;" : "=f"(r) : "f"(x));
    return r;
}

// ---------------------------------------------------------------------------
// Conversion kernels: fp32 -> fp16 single-rounded, tiled + SW128 pre-swizzled
// ---------------------------------------------------------------------------
__global__ __launch_bounds__(256) void conv_a_kernel(const float* __restrict__ u) {
    int idx = blockIdx.x * 256 + threadIdx.x;      // 8,388,608 threads
    int m = idx >> 8;
    int k = (idx & 255) * 2;
    float2 v = *(const float2*)(u + (size_t)m * IN_DIM + k);
    __half h0 = __float2half_rn(v.x);
    __half h1 = __float2half_rn(v.y);
    uint32_t hp = (uint32_t)*(unsigned short*)&h0 | ((uint32_t)*(unsigned short*)&h1 << 16);
    int mt = m >> 7, r = m & 127;
    int ch = k >> 6, c = k & 63;
    uint32_t off = swz((uint32_t)(r * 128 + c * 2));
    char* base = (char*)g_A2;
    *(uint32_t*)(base + (((size_t)(mt * 8 + ch)) << 14) + off) = hp;
}

__global__ __launch_bounds__(256) void conv_w_kernel(const float* __restrict__ W) {
    int idx = blockIdx.x * 256 + threadIdx.x;      // 524,288 threads
    int n = idx >> 8;
    int k = (idx & 255) * 2;
    float2 v = *(const float2*)(W + (size_t)n * IN_DIM + k);
    __half h0 = __float2half_rn(v.x);
    __half h1 = __float2half_rn(v.y);
    uint32_t hp = (uint32_t)*(unsigned short*)&h0 | ((uint32_t)*(unsigned short*)&h1 << 16);
    int nt = n >> 7, r = n & 127;
    int ch = k >> 6, c = k & 63;
    uint32_t off = swz((uint32_t)(r * 128 + c * 2));
    char* base = (char*)g_W2;
    *(uint32_t*)(base + (((size_t)(nt * 8 + ch)) << 14) + off) = hp;
}

// ---------------------------------------------------------------------------
// fp16 warp-MMA GEMM, two-phase, in-register sb.
// CTA tile 128x128, BK=64, 128 threads (4 warps, 2x2, warp tile 64x64).
// Phase A (chunks 0-7):  acc = A * W_c1 -> sb = 5*tanh((acc+b)/5) packed to regs
// Phase B (chunks 8-15): acc = A * W_io -> store uint2{(sb0,io0),(sb1,io1)}
// 3-stage cp.async pipeline, 96 KB smem, 2 CTAs/SM. Grid (8, 512).
// ---------------------------------------------------------------------------
#define NST 3
#define STAGE_BYTES 32768                     // A 16KB + B 16KB
#define SMEM_TOTAL (NST * STAGE_BYTES)        // 96 KB

__global__ __launch_bounds__(128, 2) void gemm_mma_kernel(const float* __restrict__ bias) {
    extern __shared__ __align__(1024) char smem[];
    const uint32_t sm   = smem_u32(smem);
    const int tid  = threadIdx.x;
    const int wid  = tid >> 5;
    const int lane = tid & 31;
    const int nt   = blockIdx.x;     // 0..7  (mem cols nt*128..nt*128+127)
    const int mt   = blockIdx.y;     // 0..511
    const int wm   = wid >> 1;       // 0..1
    const int wn   = wid & 1;        // 0..1

    const char* Ab    = (const char*)g_A2 + ((size_t)mt << 17);        // mt * 8 * 16KB
    const char* Bb_c1 = (const char*)g_W2 + ((size_t)nt << 17);        // wt = nt
    const char* Bb_io = (const char*)g_W2 + ((size_t)(nt + 8) << 17);  // wt = nt + 8

    float acc[4][8][4];
#pragma unroll
    for (int i = 0; i < 4; i++)
#pragma unroll
        for (int j = 0; j < 8; j++)
#pragma unroll
            for (int e = 0; e < 4; e++) acc[i][j][e] = 0.0f;

    uint32_t sbs[4][8][2];           // packed half2 sb, filled at end of phase A

    // ldmatrix per-lane addressing (SW128): phys = row*128 + ((c16 ^ (row&7))*16)
    const int jj = lane >> 3;        // matrix index 0..3
    const int rl = lane & 7;
    uint32_t arow[4], brow[4];
#pragma unroll
    for (int mi = 0; mi < 4; mi++)
        arow[mi] = (uint32_t)((wm * 64 + mi * 16 + (jj & 1) * 8 + rl) * 128);
#pragma unroll
    for (int p = 0; p < 4; p++)
        brow[p] = (uint32_t)((wn * 64 + p * 16 + (jj & 1) * 8 + rl) * 128);

    auto load_stage = [&](int c, int s) {
        const char* As = Ab + ((size_t)(c & 7) << 14);
        const char* Bs = (c < 8) ? (Bb_c1 + ((size_t)c << 14))
                                 : (Bb_io + ((size_t)(c - 8) << 14));
        uint32_t dst = sm + (uint32_t)s * STAGE_BYTES;
#pragma unroll
        for (int i = 0; i < 8; i++) {
            uint32_t off = (uint32_t)(tid + i * 128) * 16;
            cp_async16(dst + off, As + off);
        }
#pragma unroll
        for (int i = 0; i < 8; i++) {
            uint32_t off = (uint32_t)(tid + i * 128) * 16;
            cp_async16(dst + 16384 + off, Bs + off);
        }
        cp_commit();
    };

    load_stage(0, 0);
    load_stage(1, 1);

    for (int ck = 0; ck < NCHUNK; ck++) {
        const int s = ck % NST;
        cp_wait<1>();
        __syncthreads();
        if (ck + 2 < NCHUNK) load_stage(ck + 2, (ck + 2) % NST);

        const uint32_t sA = sm + (uint32_t)s * STAGE_BYTES;
        const uint32_t sB = sA + 16384;

#pragma unroll
        for (int ks = 0; ks < 4; ks++) {
            const uint32_t cb = (uint32_t)(((2 * ks + (jj >> 1)) ^ rl) * 16);
            uint32_t a[4][4], br[4][4];
#pragma unroll
            for (int mi = 0; mi < 4; mi++)
                LDSM4(a[mi][0], a[mi][1], a[mi][2], a[mi][3], sA + arow[mi] + cb);
#pragma unroll
            for (int p = 0; p < 4; p++)
                LDSM4(br[p][0], br[p][1], br[p][2], br[p][3], sB + brow[p] + cb);
#pragma unroll
            for (int mi = 0; mi < 4; mi++) {
#pragma unroll
                for (int ni = 0; ni < 8; ni++) {
                    const int p = ni >> 1, sub = ni & 1;
                    MMA16816(acc[mi][ni][0], acc[mi][ni][1], acc[mi][ni][2], acc[mi][ni][3],
                             a[mi][0], a[mi][1], a[mi][2], a[mi][3],
                             br[p][sub], br[p][sub + 2]);
                }
            }
        }

        // Phase-A epilogue: sb -> packed half2 registers, reset acc for phase B.
        if (ck == 7) {
            const int n0 = nt * 128;
#pragma unroll
            for (int mi = 0; mi < 4; mi++) {
#pragma unroll
                for (int ni = 0; ni < 8; ni++) {
                    const int col = n0 + wn * 64 + ni * 8 + (lane & 3) * 2;
                    const float2 b2 = *(const float2*)(bias + col);
                    float s0 = 5.0f * tanh_fast((acc[mi][ni][0] + b2.x) * 0.2f);
                    float s1 = 5.0f * tanh_fast((acc[mi][ni][1] + b2.y) * 0.2f);
                    float s2 = 5.0f * tanh_fast((acc[mi][ni][2] + b2.x) * 0.2f);
                    float s3 = 5.0f * tanh_fast((acc[mi][ni][3] + b2.y) * 0.2f);
                    __half2 p01 = __floats2half2_rn(s0, s1);
                    __half2 p23 = __floats2half2_rn(s2, s3);
                    sbs[mi][ni][0] = *(uint32_t*)&p01;
                    sbs[mi][ni][1] = *(uint32_t*)&p23;
                    acc[mi][ni][0] = 0.0f; acc[mi][ni][1] = 0.0f;
                    acc[mi][ni][2] = 0.0f; acc[mi][ni][3] = 0.0f;
                }
            }
        }
    }

    // Final epilogue: io = acc + bias_io; store uint2 pairs (sb,io)(sb,io).
    const int n0 = nt * 128;
#pragma unroll
    for (int mi = 0; mi < 4; mi++) {
        const int row0 = mt * 128 + wm * 64 + mi * 16 + (lane >> 2);
#pragma unroll
        for (int ni = 0; ni < 8; ni++) {
            const int memc = n0 + wn * 64 + ni * 8 + (lane & 3) * 2;
            const float2 b2 = *(const float2*)(bias + MEM + memc);
            uint32_t io0 = (uint32_t)__half_as_ushort(__float2half_rn(acc[mi][ni][0] + b2.x));
            uint32_t io1 = (uint32_t)__half_as_ushort(__float2half_rn(acc[mi][ni][1] + b2.y));
            uint32_t io2 = (uint32_t)__half_as_ushort(__float2half_rn(acc[mi][ni][2] + b2.x));
            uint32_t io3 = (uint32_t)__half_as_ushort(__float2half_rn(acc[mi][ni][3] + b2.y));
            uint32_t s01 = sbs[mi][ni][0];
            uint32_t s23 = sbs[mi][ni][1];
            uint2 w0, w1;
            w0.x = (s01 & 0xFFFFu) | (io0 << 16);   // (sb0, io0)
            w0.y = (s01 >> 16)     | (io1 << 16);   // (sb1, io1)
            w1.x = (s23 & 0xFFFFu) | (io2 << 16);   // (sb2, io2)
            w1.y = (s23 >> 16)     | (io3 << 16);   // (sb3, io3)
            __stcs((uint2*)&g_embh2[(size_t)row0 * MEM + memc],       w0);
            __stcs((uint2*)&g_embh2[(size_t)(row0 + 8) * MEM + memc], w1);
        }
    }
}

// ---------------------------------------------------------------------------
// Phase 2: sequential scan over L. One thread per (b, mem) lane (round-13
// shape — 256-thread blocks, 28 warps/SM). __ldg on the (sb,io) stream so the
// compiler can hoist loads past the h_t stores (no alias serialization).
//   hfn = tanh(x),  eps = 1.35 + 0.45*tanh(5(hf-0.5)),  hsn = hs + eps*(hf-hs)
// out layout: h_t [B][L][MEM] ++ hf_last [B][MEM]
// ---------------------------------------------------------------------------
__global__ __launch_bounds__(256) void scan_kernel(const float* __restrict__ h0,
                                                   float* __restrict__ out)
{
    const int idx = blockIdx.x * 256 + threadIdx.x;
    const int b   = idx >> 10;

    float hf = h0[idx];
    float hs = h0[B_DIM * MEM + idx];

    const __half2* e = g_embh2 + (size_t)b * L_DIM * MEM + (idx & (MEM - 1));
    float*         o = out     + (size_t)b * L_DIM * MEM + (idx & (MEM - 1));

#pragma unroll 8
    for (int l = 0; l < L_DIM; l++) {
        const float2 v = __half22float2(__ldg(e + (size_t)l * MEM));

        const float hsb = hs + 0.4f;
        const float x   = v.x + v.y + 4.0f * hf - 7.0f * hsb * hsb;
        const float hfn = tanh_hw(x);
        const float eps = fmaf(0.45f, tanh_hw((hf - 0.5f) * 5.0f), 1.35f);
        const float hsn = fmaf(eps, hf - hs, hs);

        o[(size_t)l * MEM] = hfn;
        hf = hfn;
        hs = hsn;
    }
    out[(size_t)M_DIM * MEM + idx] = hf;
}

// ---------------------------------------------------------------------------
// Launch
// ---------------------------------------------------------------------------
extern "C" void kernel_launch(void* const* d_in, const int* in_sizes, int n_in,
                              void* d_out, int out_size)
{
    const float* u    = (const float*)d_in[0];   // (128, 512, 512)
    const float* h0   = (const float*)d_in[1];   // (2, 128, 1024)
    const float* W    = (const float*)d_in[2];   // (2048, 512)
    const float* bias = (const float*)d_in[3];   // (2048,)
    float* out = (float*)d_out;

    cudaFuncSetAttribute(gemm_mma_kernel, cudaFuncAttributeMaxDynamicSharedMemorySize, SMEM_TOTAL);

    conv_a_kernel<<<(M_DIM * IN_DIM / 2) / 256, 256>>>(u);   // 32768 blocks
    conv_w_kernel<<<(NOUT * IN_DIM / 2) / 256, 256>>>(W);    // 2048 blocks

    dim3 grid(8, 512);
    gemm_mma_kernel<<<grid, 128, SMEM_TOTAL>>>(bias);

    scan_kernel<<<(B_DIM * MEM) / 256, 256>>>(h0, out);
}

// round 16
// speedup vs baseline: 1.0383x; 1.0165x over previous
#include <cuda_runtime.h>
#include <cuda_fp16.h>
#include <cstdint>
#include <cstddef>

// ---------------------------------------------------------------------------
// Problem dims
// ---------------------------------------------------------------------------
#define B_DIM   128
#define L_DIM   512
#define IN_DIM  512
#define MEM     1024
#define NOUT    2048
#define M_DIM   (B_DIM * L_DIM)      // 65536

#define NCHUNK  16                   // 8 chunks c1-phase + 8 chunks io-phase

// ---------------------------------------------------------------------------
// Device scratch (static allocation — no runtime alloc)
// g_embh2: [M][1024] __half2 — .x = sb = 5*tanh((c1+b)/5), .y = io + b_io
// g_A2   : [mt(512)][chunk(8)][128 rows][64 cols] fp16, SW128-swizzled 16KB blocks
// g_W2   : [wt(16)][chunk(8)][128 rows][64 cols] fp16 (wt 0-7 = c1 cols, 8-15 = io)
// ---------------------------------------------------------------------------
__device__ __half2 g_embh2[(size_t)M_DIM * MEM];    // 256 MB
__device__ __half  g_A2[(size_t)M_DIM * 512];       // 64 MB
__device__ __half  g_W2[(size_t)NOUT * 512];        // 2 MB

// ---------------------------------------------------------------------------
// Helpers
// ---------------------------------------------------------------------------
__device__ __forceinline__ uint32_t smem_u32(const void* p) {
    uint32_t a;
    asm("{ .reg .u64 t; cvta.to.shared.u64 t, %1; cvt.u32.u64 %0, t; }" : "=r"(a) : "l"(p));
    return a;
}
__device__ __forceinline__ uint32_t swz(uint32_t b) { return b ^ ((b >> 3) & 0x70); }

__device__ __forceinline__ void cp_async16(uint32_t dst, const void* src) {
    asm volatile("cp.async.cg.shared.global [%0], [%1], 16;" :: "r"(dst), "l"(src) : "memory");
}
__device__ __forceinline__ void cp_commit() {
    asm volatile("cp.async.commit_group;" ::: "memory");
}
template <int N>
__device__ __forceinline__ void cp_wait() {
    asm volatile("cp.async.wait_group %0;" :: "n"(N) : "memory");
}

#define LDSM4(r0, r1, r2, r3, a) \
    asm volatile("ldmatrix.sync.aligned.m8n8.x4.shared.b16 {%0,%1,%2,%3}, [%4];" \
                 : "=r"(r0), "=r"(r1), "=r"(r2), "=r"(r3) : "r"(a))

#define MMA16816(c0, c1, c2, c3, a0, a1, a2, a3, b0, b1) \
    asm volatile("mma.sync.aligned.m16n8k16.row.col.f32.f16.f16.f32 " \
                 "{%0,%1,%2,%3}, {%4,%5,%6,%7}, {%8,%9}, {%0,%1,%2,%3};" \
                 : "+f"(c0), "+f"(c1), "+f"(c2), "+f"(c3) \
                 : "r"(a0), "r"(a1), "r"(a2), "r"(a3), "r"(b0), "r"(b1))

// Accurate fast tanh (epilogue only; error ~1e-6)
__device__ __forceinline__ float tanh_fast(float x) {
    float a = fabsf(x);
    float e = __expf(-2.0f * a);
    float r = __fdividef(1.0f - e, 1.0f + e);
    return copysignf(r, x);
}

// HW tanh (MUFU.TANH, sm_75+): single instruction
__device__ __forceinline__ float tanh_hw(float x) {
    float r;
    asm("tanh.approx.f32 %0, %1;" : "=f"(r) : "f"(x));
    return r;
}

// ---------------------------------------------------------------------------
// Conversion kernels: fp32 -> fp16 single-rounded, tiled + SW128 pre-swizzled
// ---------------------------------------------------------------------------
__global__ __launch_bounds__(256) void conv_a_kernel(const float* __restrict__ u) {
    int idx = blockIdx.x * 256 + threadIdx.x;      // 8,388,608 threads
    int m = idx >> 8;
    int k = (idx & 255) * 2;
    float2 v = *(const float2*)(u + (size_t)m * IN_DIM + k);
    __half h0 = __float2half_rn(v.x);
    __half h1 = __float2half_rn(v.y);
    uint32_t hp = (uint32_t)*(unsigned short*)&h0 | ((uint32_t)*(unsigned short*)&h1 << 16);
    int mt = m >> 7, r = m & 127;
    int ch = k >> 6, c = k & 63;
    uint32_t off = swz((uint32_t)(r * 128 + c * 2));
    char* base = (char*)g_A2;
    *(uint32_t*)(base + (((size_t)(mt * 8 + ch)) << 14) + off) = hp;
}

__global__ __launch_bounds__(256) void conv_w_kernel(const float* __restrict__ W) {
    int idx = blockIdx.x * 256 + threadIdx.x;      // 524,288 threads
    int n = idx >> 8;
    int k = (idx & 255) * 2;
    float2 v = *(const float2*)(W + (size_t)n * IN_DIM + k);
    __half h0 = __float2half_rn(v.x);
    __half h1 = __float2half_rn(v.y);
    uint32_t hp = (uint32_t)*(unsigned short*)&h0 | ((uint32_t)*(unsigned short*)&h1 << 16);
    int nt = n >> 7, r = n & 127;
    int ch = k >> 6, c = k & 63;
    uint32_t off = swz((uint32_t)(r * 128 + c * 2));
    char* base = (char*)g_W2;
    *(uint32_t*)(base + (((size_t)(nt * 8 + ch)) << 14) + off) = hp;
}

// ---------------------------------------------------------------------------
// fp16 warp-MMA GEMM, two-phase, in-register sb, FRAGMENT DOUBLE-BUFFERING.
// CTA tile 128x128, BK=64, 256 threads (8 warps, 2(m) x 4(n), warp tile 64x32).
// Phase A (chunks 0-7):  acc = A * W_c1 -> sb = 5*tanh((acc+b)/5) packed to regs
// Phase B (chunks 8-15): acc = A * W_io -> store uint2{(sb0,io0),(sb1,io1)}
// 3-stage cp.async pipeline, 96 KB smem, 2 CTAs/SM. Grid (8, 512).
// ---------------------------------------------------------------------------
#define NST 3
#define STAGE_BYTES 32768                     // A 16KB + B 16KB
#define SMEM_TOTAL (NST * STAGE_BYTES)        // 96 KB

__global__ __launch_bounds__(256, 2) void gemm_mma_kernel(const float* __restrict__ bias) {
    extern __shared__ __align__(1024) char smem[];
    const uint32_t sm   = smem_u32(smem);
    const int tid  = threadIdx.x;
    const int wid  = tid >> 5;
    const int lane = tid & 31;
    const int nt   = blockIdx.x;     // 0..7  (mem cols nt*128..nt*128+127)
    const int mt   = blockIdx.y;     // 0..511
    const int wm   = wid >> 2;       // 0..1
    const int wn   = wid & 3;        // 0..3

    const char* Ab    = (const char*)g_A2 + ((size_t)mt << 17);        // mt * 8 * 16KB
    const char* Bb_c1 = (const char*)g_W2 + ((size_t)nt << 17);        // wt = nt
    const char* Bb_io = (const char*)g_W2 + ((size_t)(nt + 8) << 17);  // wt = nt + 8

    float acc[4][4][4];
#pragma unroll
    for (int i = 0; i < 4; i++)
#pragma unroll
        for (int j = 0; j < 4; j++)
#pragma unroll
            for (int e = 0; e < 4; e++) acc[i][j][e] = 0.0f;

    uint32_t sbs[4][4][2];           // packed half2 sb, filled at end of phase A

    // ldmatrix per-lane addressing (SW128): phys = row*128 + ((c16 ^ (row&7))*16)
    const int jj = lane >> 3;        // matrix index 0..3
    const int rl = lane & 7;
    uint32_t arow[4], brow[2];
#pragma unroll
    for (int mi = 0; mi < 4; mi++)
        arow[mi] = (uint32_t)((wm * 64 + mi * 16 + (jj & 1) * 8 + rl) * 128);
#pragma unroll
    for (int p = 0; p < 2; p++)
        brow[p] = (uint32_t)((wn * 32 + p * 16 + (jj & 1) * 8 + rl) * 128);

    auto load_stage = [&](int c, int s) {
        const char* As = Ab + ((size_t)(c & 7) << 14);
        const char* Bs = (c < 8) ? (Bb_c1 + ((size_t)c << 14))
                                 : (Bb_io + ((size_t)(c - 8) << 14));
        uint32_t dst = sm + (uint32_t)s * STAGE_BYTES;
#pragma unroll
        for (int i = 0; i < 4; i++) {
            uint32_t off = (uint32_t)(tid + i * 256) * 16;
            cp_async16(dst + off, As + off);
        }
#pragma unroll
        for (int i = 0; i < 4; i++) {
            uint32_t off = (uint32_t)(tid + i * 256) * 16;
            cp_async16(dst + 16384 + off, Bs + off);
        }
        cp_commit();
    };

    load_stage(0, 0);
    load_stage(1, 1);

    // double-buffered fragments
    uint32_t a[2][4][4], br[2][2][4];

    for (int ck = 0; ck < NCHUNK; ck++) {
        const int s = ck % NST;
        cp_wait<1>();
        __syncthreads();
        if (ck + 2 < NCHUNK) load_stage(ck + 2, (ck + 2) % NST);

        const uint32_t sA = sm + (uint32_t)s * STAGE_BYTES;
        const uint32_t sB = sA + 16384;

        auto ldfrag = [&](int ks, int bi) {
            const uint32_t cb = (uint32_t)(((2 * ks + (jj >> 1)) ^ rl) * 16);
#pragma unroll
            for (int mi = 0; mi < 4; mi++)
                LDSM4(a[bi][mi][0], a[bi][mi][1], a[bi][mi][2], a[bi][mi][3],
                      sA + arow[mi] + cb);
#pragma unroll
            for (int p = 0; p < 2; p++)
                LDSM4(br[bi][p][0], br[bi][p][1], br[bi][p][2], br[bi][p][3],
                      sB + brow[p] + cb);
        };

        ldfrag(0, 0);
#pragma unroll
        for (int ks = 0; ks < 4; ks++) {
            const int bi = ks & 1;
            if (ks < 3) ldfrag(ks + 1, (ks + 1) & 1);
#pragma unroll
            for (int mi = 0; mi < 4; mi++) {
#pragma unroll
                for (int ni = 0; ni < 4; ni++) {
                    const int p = ni >> 1, sub = ni & 1;
                    MMA16816(acc[mi][ni][0], acc[mi][ni][1], acc[mi][ni][2], acc[mi][ni][3],
                             a[bi][mi][0], a[bi][mi][1], a[bi][mi][2], a[bi][mi][3],
                             br[bi][p][sub], br[bi][p][sub + 2]);
                }
            }
        }

        // Phase-A epilogue: sb -> packed half2 registers, reset acc for phase B.
        if (ck == 7) {
            const int n0 = nt * 128;
#pragma unroll
            for (int mi = 0; mi < 4; mi++) {
#pragma unroll
                for (int ni = 0; ni < 4; ni++) {
                    const int col = n0 + wn * 32 + ni * 8 + (lane & 3) * 2;
                    const float2 b2 = *(const float2*)(bias + col);
                    float s0 = 5.0f * tanh_fast((acc[mi][ni][0] + b2.x) * 0.2f);
                    float s1 = 5.0f * tanh_fast((acc[mi][ni][1] + b2.y) * 0.2f);
                    float s2 = 5.0f * tanh_fast((acc[mi][ni][2] + b2.x) * 0.2f);
                    float s3 = 5.0f * tanh_fast((acc[mi][ni][3] + b2.y) * 0.2f);
                    __half2 p01 = __floats2half2_rn(s0, s1);
                    __half2 p23 = __floats2half2_rn(s2, s3);
                    sbs[mi][ni][0] = *(uint32_t*)&p01;
                    sbs[mi][ni][1] = *(uint32_t*)&p23;
                    acc[mi][ni][0] = 0.0f; acc[mi][ni][1] = 0.0f;
                    acc[mi][ni][2] = 0.0f; acc[mi][ni][3] = 0.0f;
                }
            }
        }
    }

    // Final epilogue: io = acc + bias_io; store uint2 pairs (sb,io)(sb,io).
    const int n0 = nt * 128;
#pragma unroll
    for (int mi = 0; mi < 4; mi++) {
        const int row0 = mt * 128 + wm * 64 + mi * 16 + (lane >> 2);
#pragma unroll
        for (int ni = 0; ni < 4; ni++) {
            const int memc = n0 + wn * 32 + ni * 8 + (lane & 3) * 2;
            const float2 b2 = *(const float2*)(bias + MEM + memc);
            uint32_t io0 = (uint32_t)__half_as_ushort(__float2half_rn(acc[mi][ni][0] + b2.x));
            uint32_t io1 = (uint32_t)__half_as_ushort(__float2half_rn(acc[mi][ni][1] + b2.y));
            uint32_t io2 = (uint32_t)__half_as_ushort(__float2half_rn(acc[mi][ni][2] + b2.x));
            uint32_t io3 = (uint32_t)__half_as_ushort(__float2half_rn(acc[mi][ni][3] + b2.y));
            uint32_t s01 = sbs[mi][ni][0];
            uint32_t s23 = sbs[mi][ni][1];
            uint2 w0, w1;
            w0.x = (s01 & 0xFFFFu) | (io0 << 16);   // (sb0, io0)
            w0.y = (s01 >> 16)     | (io1 << 16);   // (sb1, io1)
            w1.x = (s23 & 0xFFFFu) | (io2 << 16);   // (sb2, io2)
            w1.y = (s23 >> 16)     | (io3 << 16);   // (sb3, io3)
            __stcs((uint2*)&g_embh2[(size_t)row0 * MEM + memc],       w0);
            __stcs((uint2*)&g_embh2[(size_t)(row0 + 8) * MEM + memc], w1);
        }
    }
}

// ---------------------------------------------------------------------------
// Phase 2: sequential scan over L. One thread per (b, mem) lane.
//   hfn = tanh(x),  eps = 1.35 + 0.45*tanh(5(hf-0.5)),  hsn = hs + eps*(hf-hs)
// out layout: h_t [B][L][MEM] ++ hf_last [B][MEM]
// ---------------------------------------------------------------------------
__global__ __launch_bounds__(256) void scan_kernel(const float* __restrict__ h0,
                                                   float* __restrict__ out)
{
    const int idx = blockIdx.x * 256 + threadIdx.x;
    const int b   = idx >> 10;

    float hf = h0[idx];
    float hs = h0[B_DIM * MEM + idx];

    const __half2* e = g_embh2 + (size_t)b * L_DIM * MEM + (idx & (MEM - 1));
    float*         o = out     + (size_t)b * L_DIM * MEM + (idx & (MEM - 1));

#pragma unroll 8
    for (int l = 0; l < L_DIM; l++) {
        const float2 v = __half22float2(__ldg(e + (size_t)l * MEM));

        const float hsb = hs + 0.4f;
        const float x   = v.x + v.y + 4.0f * hf - 7.0f * hsb * hsb;
        const float hfn = tanh_hw(x);
        const float eps = fmaf(0.45f, tanh_hw((hf - 0.5f) * 5.0f), 1.35f);
        const float hsn = fmaf(eps, hf - hs, hs);

        o[(size_t)l * MEM] = hfn;
        hf = hfn;
        hs = hsn;
    }
    out[(size_t)M_DIM * MEM + idx] = hf;
}

// ---------------------------------------------------------------------------
// Launch
// ---------------------------------------------------------------------------
extern "C" void kernel_launch(void* const* d_in, const int* in_sizes, int n_in,
                              void* d_out, int out_size)
{
    const float* u    = (const float*)d_in[0];   // (128, 512, 512)
    const float* h0   = (const float*)d_in[1];   // (2, 128, 1024)
    const float* W    = (const float*)d_in[2];   // (2048, 512)
    const float* bias = (const float*)d_in[3];   // (2048,)
    float* out = (float*)d_out;

    cudaFuncSetAttribute(gemm_mma_kernel, cudaFuncAttributeMaxDynamicSharedMemorySize, SMEM_TOTAL);

    conv_a_kernel<<<(M_DIM * IN_DIM / 2) / 256, 256>>>(u);   // 32768 blocks
    conv_w_kernel<<<(NOUT * IN_DIM / 2) / 256, 256>>>(W);    // 2048 blocks

    dim3 grid(8, 512);
    gemm_mma_kernel<<<grid, 256, SMEM_TOTAL>>>(bias);

    scan_kernel<<<(B_DIM * MEM) / 256, 256>>>(h0, out);
}